// round 7
// baseline (speedup 1.0000x reference)
#include <cuda_runtime.h>
#include <cuda_bf16.h>
#include <math.h>
#include <stdint.h>

// Problem constants
#define NB   64
#define NT   1024
#define AD   128
#define RD   1024
#define ED   512
#define NF   32
#define KSZ  31
#define PADW 15

#define KTOT 544          // 512 keys + 32 loc features
#define NCH  17           // 17 chunks of K=32
#define TM   128          // t rows per CTA tile

#define NCHUNKS 4         // batch pipeline chunks
#define BPC     (NB / NCHUNKS)

// Tile strides (bytes): 32 bf16 data + 8 pad = 80B rows.
#define TSTRIDE 80
#define TILE_B  (128 * TSTRIDE)
#define DYN_BYTES (4 * TILE_B)

// ---------------- device scratch ----------------
__device__ __nv_bfloat16 g_Wbf[AD][KTOT];
__device__ float g_qproj[NB][AD];
__device__ float g_scores[NB][NT];
__device__ float g_partial[NB][16][ED];

// ---------------- helpers ----------------
__device__ __forceinline__ uint32_t smem_u32(const void* p) {
    uint32_t a;
    asm("{ .reg .u64 t; cvta.to.shared.u64 t, %1; cvt.u32.u64 %0, t; }"
        : "=r"(a) : "l"(p));
    return a;
}
__device__ __forceinline__ void sts64(uint32_t a, uint32_t x, uint32_t y) {
    asm volatile("st.shared.v2.b32 [%0], {%1,%2};" :: "r"(a), "r"(x), "r"(y));
}
__device__ __forceinline__ void sts32(uint32_t a, uint32_t x) {
    asm volatile("st.shared.b32 [%0], %1;" :: "r"(a), "r"(x));
}
__device__ __forceinline__ void cp16(uint32_t dst, const void* src) {
    asm volatile("cp.async.ca.shared.global [%0], [%1], 16;" :: "r"(dst), "l"(src));
}
__device__ __forceinline__ void ldsm4(uint32_t r[4], uint32_t addr) {
    asm volatile("ldmatrix.sync.aligned.m8n8.x4.shared.b16 {%0,%1,%2,%3}, [%4];"
                 : "=r"(r[0]), "=r"(r[1]), "=r"(r[2]), "=r"(r[3]) : "r"(addr));
}
__device__ __forceinline__ void mma_bf16(float d[4], const uint32_t a[4],
                                         uint32_t b0, uint32_t b1) {
    asm volatile(
        "mma.sync.aligned.m16n8k16.row.col.f32.bf16.bf16.f32 "
        "{%0,%1,%2,%3}, {%4,%5,%6,%7}, {%8,%9}, {%0,%1,%2,%3};"
        : "+f"(d[0]), "+f"(d[1]), "+f"(d[2]), "+f"(d[3])
        : "r"(a[0]), "r"(a[1]), "r"(a[2]), "r"(a[3]), "r"(b0), "r"(b1));
}
__device__ __forceinline__ uint32_t pack_bf2(float x, float y) {
    __nv_bfloat162 p = __float22bfloat162_rn(make_float2(x, y));
    return *(uint32_t*)&p;
}

// ---------------------------------------------------------------------------
__global__ __launch_bounds__(128) void k_prep(const float* __restrict__ query,
                                              const float* __restrict__ W_query,
                                              const float* __restrict__ W_key,
                                              const float* __restrict__ W_loc_proj) {
    int tid = threadIdx.x;
    if (blockIdx.x < AD) {
        int a = blockIdx.x;
        for (int k = tid; k < KTOT; k += 128) {
            float v = (k < ED) ? W_key[a * ED + k] : W_loc_proj[a * NF + (k - ED)];
            g_Wbf[a][k] = __float2bfloat16(v);
        }
        return;
    }
    __shared__ float q_s[RD];
    int b = blockIdx.x - AD;
    #pragma unroll
    for (int i = 0; i < RD / 128; i++)
        q_s[i * 128 + tid] = query[b * RD + i * 128 + tid];
    __syncthreads();
    const float4* wr = (const float4*)(W_query + (size_t)tid * RD);
    float acc = 0.f;
    #pragma unroll 8
    for (int e4 = 0; e4 < RD / 4; e4++) {
        float4 w = wr[e4];
        float4 q = *(const float4*)&q_s[e4 * 4];
        acc += w.x * q.x + w.y * q.y + w.z * q.z + w.w * q.w;
    }
    g_qproj[b][tid] = acc;
}

// ---------------------------------------------------------------------------
__global__ __launch_bounds__(256, 2) void k_scores(
    const float* __restrict__ keys,
    const float* __restrict__ awc,
    const float* __restrict__ W_loc_conv,
    const float* __restrict__ W_attn,
    const unsigned char* __restrict__ mask,
    int b0)
{
    extern __shared__ char dsm[];
    __shared__ float awc_s[158];
    __shared__ float Wc_s[NF][KSZ];
    __shared__ float qp_s[AD];
    __shared__ float wattn_s[AD];
    __shared__ float sred[2][128];

    const int b   = b0 + blockIdx.y;
    const int t0  = blockIdx.x * TM;
    const int tid = threadIdx.x;
    const int lane = tid & 31, w = tid >> 5;
    const int g = lane >> 2, tg = lane & 3;
    const int Mb = (w & 3) * 32;
    const int Nb = (w >> 2) * 64;

    const uint32_t base = smem_u32(dsm);
    const uint32_t Aoff[2] = { 0u, (uint32_t)TILE_B };
    const uint32_t Boff[2] = { 2u * TILE_B, 3u * TILE_B };

    const int lm = lane & 15;
    const int lkb = (lane >> 4) * 16;
    const int bn = (lane & 7) + ((lane >> 4) << 3);
    const int bkb = ((lane >> 3) & 1) * 16;

    if (tid < 158) {
        int gi = t0 - PADW + tid;
        awc_s[tid] = (gi >= 0 && gi < NT) ? awc[b * NT + gi] : 0.f;
    }
    if (tid < AD) { qp_s[tid] = g_qproj[b][tid]; wattn_s[tid] = W_attn[tid]; }
    for (int i = tid; i < NF * KSZ; i += 256)
        Wc_s[i / KSZ][i % KSZ] = W_loc_conv[i];

    const int ar = tid >> 3;
    const int akq = (tid & 7) << 2;
    const float* kptr = keys + ((size_t)(b * NT + t0 + ar)) * ED + akq;

    const int bnrow = tid >> 2;
    const int bur = tid & 3;

    float4 ka[4];
    #pragma unroll
    for (int j = 0; j < 4; j++)
        ka[j] = *(const float4*)(kptr + (size_t)(32 * j) * ED);
    #pragma unroll
    for (int j = 0; j < 2; j++)
        cp16(base + Boff[0] + (bnrow + 64 * j) * TSTRIDE + bur * 16,
             &g_Wbf[bnrow + 64 * j][bur * 8]);
    asm volatile("cp.async.commit_group;");

    float acc[2][8][4];
    #pragma unroll
    for (int mt = 0; mt < 2; mt++)
        #pragma unroll
        for (int nt = 0; nt < 8; nt++)
            #pragma unroll
            for (int ci = 0; ci < 4; ci++) acc[mt][nt][ci] = 0.f;

    for (int c = 0; c < NCH; c++) {
        const int buf = c & 1;
        asm volatile("cp.async.wait_group 0;");
        __syncthreads();

        if (c < 16) {
            #pragma unroll
            for (int j = 0; j < 4; j++) {
                uint32_t p0 = pack_bf2(ka[j].x, ka[j].y);
                uint32_t p1 = pack_bf2(ka[j].z, ka[j].w);
                sts64(base + Aoff[buf] + (ar + 32 * j) * TSTRIDE + akq * 2, p0, p1);
            }
        } else {
            #pragma unroll
            for (int j = 0; j < 8; j++) {
                int pidx = tid + 256 * j;
                int r = pidx >> 4, f = (pidx & 15) << 1;
                float s0 = 0.f, s1 = 0.f;
                #pragma unroll
                for (int k = 0; k < KSZ; k++) {
                    float av = awc_s[r + k];
                    s0 += av * Wc_s[f][k];
                    s1 += av * Wc_s[f + 1][k];
                }
                sts32(base + Aoff[buf] + r * TSTRIDE + f * 2, pack_bf2(s0, s1));
            }
        }

        if (c + 1 < 16) {
            #pragma unroll
            for (int j = 0; j < 4; j++)
                ka[j] = *(const float4*)(kptr + (size_t)(32 * j) * ED + (c + 1) * 32);
        }
        if (c + 1 < NCH) {
            #pragma unroll
            for (int j = 0; j < 2; j++)
                cp16(base + Boff[(c + 1) & 1] + (bnrow + 64 * j) * TSTRIDE + bur * 16,
                     &g_Wbf[bnrow + 64 * j][(c + 1) * 32 + bur * 8]);
        }
        asm volatile("cp.async.commit_group;");
        __syncthreads();

        const uint32_t Ab = base + Aoff[buf];
        const uint32_t Bb = base + Boff[buf];
        #pragma unroll
        for (int k16 = 0; k16 < 2; k16++) {
            uint32_t a[2][4];
            #pragma unroll
            for (int mt = 0; mt < 2; mt++)
                ldsm4(a[mt], Ab + (Mb + mt * 16 + lm) * TSTRIDE + k16 * 32 + lkb);
            #pragma unroll
            for (int g16 = 0; g16 < 4; g16++) {
                uint32_t bb[4];
                ldsm4(bb, Bb + (Nb + g16 * 16 + bn) * TSTRIDE + k16 * 32 + bkb);
                mma_bf16(acc[0][2 * g16],     a[0], bb[0], bb[1]);
                mma_bf16(acc[1][2 * g16],     a[1], bb[0], bb[1]);
                mma_bf16(acc[0][2 * g16 + 1], a[0], bb[2], bb[3]);
                mma_bf16(acc[1][2 * g16 + 1], a[1], bb[2], bb[3]);
            }
        }
    }

    #pragma unroll
    for (int mt = 0; mt < 2; mt++) {
        #pragma unroll
        for (int h = 0; h < 2; h++) {
            float p = 0.f;
            #pragma unroll
            for (int nt = 0; nt < 8; nt++) {
                int col = Nb + nt * 8 + 2 * tg;
                p += wattn_s[col]     * tanhf(acc[mt][nt][2 * h]     + qp_s[col]);
                p += wattn_s[col + 1] * tanhf(acc[mt][nt][2 * h + 1] + qp_s[col + 1]);
            }
            p += __shfl_xor_sync(0xffffffffu, p, 1);
            p += __shfl_xor_sync(0xffffffffu, p, 2);
            if (tg == 0)
                sred[w >> 2][Mb + mt * 16 + g + 8 * h] = p;
        }
    }
    __syncthreads();
    if (tid < 128) {
        int t = t0 + tid;
        float sc = sred[0][tid] + sred[1][tid];
        if (mask[b * NT + t]) sc = -INFINITY;
        g_scores[b][t] = sc;
    }
}

// ---------------------------------------------------------------------------
__global__ __launch_bounds__(256) void k_softmax(float* __restrict__ attn_out, int b0) {
    __shared__ float red[256];
    int b = b0 + blockIdx.x, tid = threadIdx.x;
    float v[4];
    float m = -INFINITY;
    #pragma unroll
    for (int i = 0; i < 4; i++) {
        v[i] = g_scores[b][i * 256 + tid];
        m = fmaxf(m, v[i]);
    }
    red[tid] = m; __syncthreads();
    for (int s = 128; s > 0; s >>= 1) {
        if (tid < s) red[tid] = fmaxf(red[tid], red[tid + s]);
        __syncthreads();
    }
    m = red[0]; __syncthreads();
    float sum = 0.f;
    #pragma unroll
    for (int i = 0; i < 4; i++) { v[i] = __expf(v[i] - m); sum += v[i]; }
    red[tid] = sum; __syncthreads();
    for (int s = 128; s > 0; s >>= 1) {
        if (tid < s) red[tid] += red[tid + s];
        __syncthreads();
    }
    float inv = 1.f / red[0];
    #pragma unroll
    for (int i = 0; i < 4; i++)
        attn_out[b * NT + i * 256 + tid] = v[i] * inv;
}

// ---------------------------------------------------------------------------
__global__ __launch_bounds__(256) void k_av(const float* __restrict__ values,
                                            const float* __restrict__ attn, int b0) {
    __shared__ float at_s[128];
    int ts = blockIdx.x, b = b0 + blockIdx.y, tid = threadIdx.x;
    if (tid < 128) at_s[tid] = attn[b * NT + ts * 128 + tid];
    __syncthreads();
    int cg = tid & 127, half = tid >> 7;
    const float4* vp = (const float4*)
        (values + ((size_t)(b * NT + ts * 128 + half * 64)) * ED);
    float4 a0 = make_float4(0.f, 0.f, 0.f, 0.f);
    float4 a1 = make_float4(0.f, 0.f, 0.f, 0.f);
    #pragma unroll 8
    for (int t = 0; t < 64; t += 2) {
        float w0 = at_s[half * 64 + t];
        float w1 = at_s[half * 64 + t + 1];
        float4 v0 = vp[(size_t)t * (ED / 4) + cg];
        float4 v1 = vp[(size_t)(t + 1) * (ED / 4) + cg];
        a0.x += w0 * v0.x; a0.y += w0 * v0.y; a0.z += w0 * v0.z; a0.w += w0 * v0.w;
        a1.x += w1 * v1.x; a1.y += w1 * v1.y; a1.z += w1 * v1.z; a1.w += w1 * v1.w;
    }
    a0.x += a1.x; a0.y += a1.y; a0.z += a1.z; a0.w += a1.w;
    *(float4*)&g_partial[b][ts * 2 + half][cg * 4] = a0;
}

// ---------------------------------------------------------------------------
__global__ __launch_bounds__(128) void k_context(const float* __restrict__ W_value,
                                                 float* __restrict__ ctx, int b0) {
    __shared__ float av_s[ED];
    int fc = blockIdx.x, b = b0 + blockIdx.y, tid = threadIdx.x;
    for (int i = tid; i < ED; i += 128) {
        float s = 0.f;
        #pragma unroll
        for (int p = 0; p < 16; p++) s += g_partial[b][p][i];
        av_s[i] = s;
    }
    __syncthreads();
    int f = fc * 128 + tid;
    const float4* wr = (const float4*)(W_value + (size_t)f * ED);
    float acc = 0.f;
    #pragma unroll 8
    for (int e4 = 0; e4 < ED / 4; e4++) {
        float4 wv = wr[e4];
        float4 a = *(const float4*)&av_s[e4 * 4];
        acc += wv.x * a.x + wv.y * a.y + wv.z * a.z + wv.w * a.w;
    }
    ctx[b * ED + f] = acc;
}

// ---------------------------------------------------------------------------
extern "C" void kernel_launch(void* const* d_in, const int* in_sizes, int n_in,
                              void* d_out, int out_size) {
    const float* query        = (const float*)d_in[0];
    const float* keys         = (const float*)d_in[1];
    const float* values       = (const float*)d_in[2];
    const float* awc          = (const float*)d_in[3];
    const unsigned char* mask = (const unsigned char*)d_in[4];
    const float* W_loc_conv   = (const float*)d_in[5];
    const float* W_loc_proj   = (const float*)d_in[6];
    const float* W_query      = (const float*)d_in[7];
    const float* W_key        = (const float*)d_in[8];
    const float* W_value      = (const float*)d_in[9];
    const float* W_attn       = (const float*)d_in[10];

    float* out      = (float*)d_out;
    float* ctx_out  = out;                 // context: 64*512
    float* attn_out = out + NB * ED;       // attn:    64*1024

    // one-time infra (created on the first, non-captured, correctness call)
    static cudaStream_t s_sc[2] = {nullptr, nullptr};
    static cudaStream_t s_post  = nullptr;
    static cudaEvent_t  ev_prep, ev_sc[NCHUNKS], ev_done;
    if (!s_post) {
        cudaStreamCreateWithFlags(&s_sc[0], cudaStreamNonBlocking);
        cudaStreamCreateWithFlags(&s_sc[1], cudaStreamNonBlocking);
        cudaStreamCreateWithFlags(&s_post, cudaStreamNonBlocking);
        cudaEventCreateWithFlags(&ev_prep, cudaEventDisableTiming);
        for (int c = 0; c < NCHUNKS; c++)
            cudaEventCreateWithFlags(&ev_sc[c], cudaEventDisableTiming);
        cudaEventCreateWithFlags(&ev_done, cudaEventDisableTiming);
        cudaFuncSetAttribute(k_scores, cudaFuncAttributeMaxDynamicSharedMemorySize,
                             DYN_BYTES);
    }

    k_prep<<<AD + NB, 128>>>(query, W_query, W_key, W_loc_proj);
    cudaEventRecord(ev_prep, 0);

    for (int c = 0; c < NCHUNKS; c++) {
        int b0 = c * BPC;
        cudaStream_t ss = s_sc[c & 1];
        cudaStreamWaitEvent(ss, ev_prep, 0);
        k_scores<<<dim3(NT / TM, BPC), 256, DYN_BYTES, ss>>>(
            keys, awc, W_loc_conv, W_attn, mask, b0);
        cudaEventRecord(ev_sc[c], ss);

        cudaStreamWaitEvent(s_post, ev_sc[c], 0);
        k_softmax<<<BPC, 256, 0, s_post>>>(attn_out, b0);
        k_av     <<<dim3(8, BPC), 256, 0, s_post>>>(values, attn_out, b0);
        k_context<<<dim3(4, BPC), 128, 0, s_post>>>(W_value, ctx_out, b0);
    }

    cudaEventRecord(ev_done, s_post);
    cudaStreamWaitEvent(0, ev_done, 0);
}

// round 8
// speedup vs baseline: 1.4830x; 1.4830x over previous
#include <cuda_runtime.h>
#include <cuda_fp16.h>
#include <math.h>
#include <stdint.h>

// Problem constants
#define NB   64
#define NT   1024
#define AD   128
#define RD   1024
#define ED   512
#define NF   32
#define KSZ  31
#define PADW 15

#define KTOT 544          // 512 keys + 32 loc features
#define NCH  17           // 17 chunks of K=32
#define TM   128          // t rows per CTA tile

// Tile strides (bytes): 32 fp16 data + 8 pad = 80B rows.
#define TSTRIDE 80
#define TILE_B  (128 * TSTRIDE)
#define DYN_BYTES (4 * TILE_B)

#define NPART 32          // k_av partials per batch

// ---------------- device scratch ----------------
__device__ __half g_Whf[AD][KTOT];
__device__ float g_qproj[NB][AD];
__device__ float g_scores[NB][NT];
__device__ float g_partial[NB][NPART][ED];

// ---------------- helpers ----------------
__device__ __forceinline__ uint32_t smem_u32(const void* p) {
    uint32_t a;
    asm("{ .reg .u64 t; cvta.to.shared.u64 t, %1; cvt.u32.u64 %0, t; }"
        : "=r"(a) : "l"(p));
    return a;
}
__device__ __forceinline__ void sts64(uint32_t a, uint32_t x, uint32_t y) {
    asm volatile("st.shared.v2.b32 [%0], {%1,%2};" :: "r"(a), "r"(x), "r"(y));
}
__device__ __forceinline__ void sts32(uint32_t a, uint32_t x) {
    asm volatile("st.shared.b32 [%0], %1;" :: "r"(a), "r"(x));
}
__device__ __forceinline__ void cp16(uint32_t dst, const void* src) {
    asm volatile("cp.async.ca.shared.global [%0], [%1], 16;" :: "r"(dst), "l"(src));
}
__device__ __forceinline__ void ldsm4(uint32_t r[4], uint32_t addr) {
    asm volatile("ldmatrix.sync.aligned.m8n8.x4.shared.b16 {%0,%1,%2,%3}, [%4];"
                 : "=r"(r[0]), "=r"(r[1]), "=r"(r[2]), "=r"(r[3]) : "r"(addr));
}
__device__ __forceinline__ void mma_f16(float d[4], const uint32_t a[4],
                                        uint32_t b0, uint32_t b1) {
    asm volatile(
        "mma.sync.aligned.m16n8k16.row.col.f32.f16.f16.f32 "
        "{%0,%1,%2,%3}, {%4,%5,%6,%7}, {%8,%9}, {%0,%1,%2,%3};"
        : "+f"(d[0]), "+f"(d[1]), "+f"(d[2]), "+f"(d[3])
        : "r"(a[0]), "r"(a[1]), "r"(a[2]), "r"(a[3]), "r"(b0), "r"(b1));
}
__device__ __forceinline__ uint32_t pack_h2(float x, float y) {
    __half2 p = __floats2half2_rn(x, y);
    return *(uint32_t*)&p;
}

// ---------------------------------------------------------------------------
__global__ __launch_bounds__(128) void k_prep(const float* __restrict__ query,
                                              const float* __restrict__ W_query,
                                              const float* __restrict__ W_key,
                                              const float* __restrict__ W_loc_proj) {
    int tid = threadIdx.x;
    if (blockIdx.x < AD) {
        int a = blockIdx.x;
        for (int k = tid; k < KTOT; k += 128) {
            float v = (k < ED) ? W_key[a * ED + k] : W_loc_proj[a * NF + (k - ED)];
            g_Whf[a][k] = __float2half(v);
        }
        return;
    }
    __shared__ float q_s[RD];
    int b = blockIdx.x - AD;
    #pragma unroll
    for (int i = 0; i < RD / 128; i++)
        q_s[i * 128 + tid] = query[b * RD + i * 128 + tid];
    __syncthreads();
    const float4* wr = (const float4*)(W_query + (size_t)tid * RD);
    float acc = 0.f;
    #pragma unroll 8
    for (int e4 = 0; e4 < RD / 4; e4++) {
        float4 w = wr[e4];
        float4 q = *(const float4*)&q_s[e4 * 4];
        acc += w.x * q.x + w.y * q.y + w.z * q.z + w.w * q.w;
    }
    g_qproj[b][tid] = acc;
}

// ---------------------------------------------------------------------------
// Scores: fp16 m16n8k16 mma + ldmatrix, 2-stage pipeline,
// fused conv-loc chunk + tanh/W_attn/mask epilogue.
__global__ __launch_bounds__(256, 2) void k_scores(
    const float* __restrict__ keys,
    const float* __restrict__ awc,
    const float* __restrict__ W_loc_conv,
    const float* __restrict__ W_attn,
    const unsigned char* __restrict__ mask)
{
    extern __shared__ char dsm[];
    __shared__ float awc_s[158];
    __shared__ float Wc_s[NF][KSZ];
    __shared__ float qp_s[AD];
    __shared__ float wattn_s[AD];
    __shared__ float sred[2][128];

    const int b   = blockIdx.y;
    const int t0  = blockIdx.x * TM;
    const int tid = threadIdx.x;
    const int lane = tid & 31, w = tid >> 5;
    const int g = lane >> 2, tg = lane & 3;
    const int Mb = (w & 3) * 32;
    const int Nb = (w >> 2) * 64;

    const uint32_t base = smem_u32(dsm);
    const uint32_t Aoff[2] = { 0u, (uint32_t)TILE_B };
    const uint32_t Boff[2] = { 2u * TILE_B, 3u * TILE_B };

    const int lm = lane & 15;
    const int lkb = (lane >> 4) * 16;
    const int bn = (lane & 7) + ((lane >> 4) << 3);
    const int bkb = ((lane >> 3) & 1) * 16;

    if (tid < 158) {
        int gi = t0 - PADW + tid;
        awc_s[tid] = (gi >= 0 && gi < NT) ? awc[b * NT + gi] : 0.f;
    }
    if (tid < AD) { qp_s[tid] = g_qproj[b][tid]; wattn_s[tid] = W_attn[tid]; }
    for (int i = tid; i < NF * KSZ; i += 256)
        Wc_s[i / KSZ][i % KSZ] = W_loc_conv[i];

    const int ar = tid >> 3;
    const int akq = (tid & 7) << 2;
    const float* kptr = keys + ((size_t)(b * NT + t0 + ar)) * ED + akq;

    const int bnrow = tid >> 2;
    const int bur = tid & 3;

    float4 ka[4];
    #pragma unroll
    for (int j = 0; j < 4; j++)
        ka[j] = *(const float4*)(kptr + (size_t)(32 * j) * ED);
    #pragma unroll
    for (int j = 0; j < 2; j++)
        cp16(base + Boff[0] + (bnrow + 64 * j) * TSTRIDE + bur * 16,
             &g_Whf[bnrow + 64 * j][bur * 8]);
    asm volatile("cp.async.commit_group;");

    float acc[2][8][4];
    #pragma unroll
    for (int mt = 0; mt < 2; mt++)
        #pragma unroll
        for (int nt = 0; nt < 8; nt++)
            #pragma unroll
            for (int ci = 0; ci < 4; ci++) acc[mt][nt][ci] = 0.f;

    for (int c = 0; c < NCH; c++) {
        const int buf = c & 1;
        asm volatile("cp.async.wait_group 0;");
        __syncthreads();

        if (c < 16) {
            #pragma unroll
            for (int j = 0; j < 4; j++) {
                uint32_t p0 = pack_h2(ka[j].x, ka[j].y);
                uint32_t p1 = pack_h2(ka[j].z, ka[j].w);
                sts64(base + Aoff[buf] + (ar + 32 * j) * TSTRIDE + akq * 2, p0, p1);
            }
        } else {
            #pragma unroll
            for (int j = 0; j < 8; j++) {
                int pidx = tid + 256 * j;
                int r = pidx >> 4, f = (pidx & 15) << 1;
                float s0 = 0.f, s1 = 0.f;
                #pragma unroll
                for (int k = 0; k < KSZ; k++) {
                    float av = awc_s[r + k];
                    s0 += av * Wc_s[f][k];
                    s1 += av * Wc_s[f + 1][k];
                }
                sts32(base + Aoff[buf] + r * TSTRIDE + f * 2, pack_h2(s0, s1));
            }
        }

        if (c + 1 < 16) {
            #pragma unroll
            for (int j = 0; j < 4; j++)
                ka[j] = *(const float4*)(kptr + (size_t)(32 * j) * ED + (c + 1) * 32);
        }
        if (c + 1 < NCH) {
            #pragma unroll
            for (int j = 0; j < 2; j++)
                cp16(base + Boff[(c + 1) & 1] + (bnrow + 64 * j) * TSTRIDE + bur * 16,
                     &g_Whf[bnrow + 64 * j][(c + 1) * 32 + bur * 8]);
        }
        asm volatile("cp.async.commit_group;");
        __syncthreads();

        const uint32_t Ab = base + Aoff[buf];
        const uint32_t Bb = base + Boff[buf];
        #pragma unroll
        for (int k16 = 0; k16 < 2; k16++) {
            uint32_t a[2][4];
            #pragma unroll
            for (int mt = 0; mt < 2; mt++)
                ldsm4(a[mt], Ab + (Mb + mt * 16 + lm) * TSTRIDE + k16 * 32 + lkb);
            #pragma unroll
            for (int g16 = 0; g16 < 4; g16++) {
                uint32_t bb[4];
                ldsm4(bb, Bb + (Nb + g16 * 16 + bn) * TSTRIDE + k16 * 32 + bkb);
                mma_f16(acc[0][2 * g16],     a[0], bb[0], bb[1]);
                mma_f16(acc[1][2 * g16],     a[1], bb[0], bb[1]);
                mma_f16(acc[0][2 * g16 + 1], a[0], bb[2], bb[3]);
                mma_f16(acc[1][2 * g16 + 1], a[1], bb[2], bb[3]);
            }
        }
    }

    #pragma unroll
    for (int mt = 0; mt < 2; mt++) {
        #pragma unroll
        for (int h = 0; h < 2; h++) {
            float p = 0.f;
            #pragma unroll
            for (int nt = 0; nt < 8; nt++) {
                int col = Nb + nt * 8 + 2 * tg;
                p += wattn_s[col]     * tanhf(acc[mt][nt][2 * h]     + qp_s[col]);
                p += wattn_s[col + 1] * tanhf(acc[mt][nt][2 * h + 1] + qp_s[col + 1]);
            }
            p += __shfl_xor_sync(0xffffffffu, p, 1);
            p += __shfl_xor_sync(0xffffffffu, p, 2);
            if (tg == 0)
                sred[w >> 2][Mb + mt * 16 + g + 8 * h] = p;
        }
    }
    __syncthreads();
    if (tid < 128) {
        int t = t0 + tid;
        float sc = sred[0][tid] + sred[1][tid];
        if (mask[b * NT + t]) sc = -INFINITY;
        g_scores[b][t] = sc;
    }
}

// ---------------------------------------------------------------------------
__global__ __launch_bounds__(256) void k_softmax(float* __restrict__ attn_out) {
    __shared__ float red[256];
    int b = blockIdx.x, tid = threadIdx.x;
    float v[4];
    float m = -INFINITY;
    #pragma unroll
    for (int i = 0; i < 4; i++) {
        v[i] = g_scores[b][i * 256 + tid];
        m = fmaxf(m, v[i]);
    }
    red[tid] = m; __syncthreads();
    for (int s = 128; s > 0; s >>= 1) {
        if (tid < s) red[tid] = fmaxf(red[tid], red[tid + s]);
        __syncthreads();
    }
    m = red[0]; __syncthreads();
    float sum = 0.f;
    #pragma unroll
    for (int i = 0; i < 4; i++) { v[i] = __expf(v[i] - m); sum += v[i]; }
    red[tid] = sum; __syncthreads();
    for (int s = 128; s > 0; s >>= 1) {
        if (tid < s) red[tid] += red[tid + s];
        __syncthreads();
    }
    float inv = 1.f / red[0];
    #pragma unroll
    for (int i = 0; i < 4; i++)
        attn_out[b * NT + i * 256 + tid] = v[i] * inv;
}

// ---------------------------------------------------------------------------
// attn @ values: 1024 blocks (64 t each), 32 partials per batch. HBM-bound.
__global__ __launch_bounds__(256) void k_av(const float* __restrict__ values,
                                            const float* __restrict__ attn) {
    __shared__ float at_s[64];
    int ts = blockIdx.x, b = blockIdx.y, tid = threadIdx.x;
    if (tid < 64) at_s[tid] = attn[b * NT + ts * 64 + tid];
    __syncthreads();
    int cg = tid & 127, half = tid >> 7;
    const float4* vp = (const float4*)
        (values + ((size_t)(b * NT + ts * 64 + half * 32)) * ED);
    float4 a0 = make_float4(0.f, 0.f, 0.f, 0.f);
    float4 a1 = make_float4(0.f, 0.f, 0.f, 0.f);
    #pragma unroll 8
    for (int t = 0; t < 32; t += 2) {
        float w0 = at_s[half * 32 + t];
        float w1 = at_s[half * 32 + t + 1];
        float4 v0 = vp[(size_t)t * (ED / 4) + cg];
        float4 v1 = vp[(size_t)(t + 1) * (ED / 4) + cg];
        a0.x += w0 * v0.x; a0.y += w0 * v0.y; a0.z += w0 * v0.z; a0.w += w0 * v0.w;
        a1.x += w1 * v1.x; a1.y += w1 * v1.y; a1.z += w1 * v1.z; a1.w += w1 * v1.w;
    }
    a0.x += a1.x; a0.y += a1.y; a0.z += a1.z; a0.w += a1.w;
    *(float4*)&g_partial[b][ts * 2 + half][cg * 4] = a0;
}

// ---------------------------------------------------------------------------
__global__ __launch_bounds__(128) void k_context(const float* __restrict__ W_value,
                                                 float* __restrict__ ctx) {
    __shared__ float av_s[ED];
    int fc = blockIdx.x, b = blockIdx.y, tid = threadIdx.x;
    for (int i = tid; i < ED; i += 128) {
        float s = 0.f;
        #pragma unroll
        for (int p = 0; p < NPART; p++) s += g_partial[b][p][i];
        av_s[i] = s;
    }
    __syncthreads();
    int f = fc * 128 + tid;
    const float4* wr = (const float4*)(W_value + (size_t)f * ED);
    float acc = 0.f;
    #pragma unroll 8
    for (int e4 = 0; e4 < ED / 4; e4++) {
        float4 wv = wr[e4];
        float4 a = *(const float4*)&av_s[e4 * 4];
        acc += wv.x * a.x + wv.y * a.y + wv.z * a.z + wv.w * a.w;
    }
    ctx[b * ED + f] = acc;
}

// ---------------------------------------------------------------------------
extern "C" void kernel_launch(void* const* d_in, const int* in_sizes, int n_in,
                              void* d_out, int out_size) {
    const float* query        = (const float*)d_in[0];
    const float* keys         = (const float*)d_in[1];
    const float* values       = (const float*)d_in[2];
    const float* awc          = (const float*)d_in[3];
    const unsigned char* mask = (const unsigned char*)d_in[4];
    const float* W_loc_conv   = (const float*)d_in[5];
    const float* W_loc_proj   = (const float*)d_in[6];
    const float* W_query      = (const float*)d_in[7];
    const float* W_key        = (const float*)d_in[8];
    const float* W_value      = (const float*)d_in[9];
    const float* W_attn       = (const float*)d_in[10];

    float* out      = (float*)d_out;
    float* ctx_out  = out;                 // context: 64*512
    float* attn_out = out + NB * ED;       // attn:    64*1024

    cudaFuncSetAttribute(k_scores, cudaFuncAttributeMaxDynamicSharedMemorySize,
                         DYN_BYTES);

    k_prep   <<<AD + NB, 128>>>(query, W_query, W_key, W_loc_proj);
    k_scores <<<dim3(NT / TM, NB), 256, DYN_BYTES>>>(keys, awc, W_loc_conv,
                                                     W_attn, mask);
    k_softmax<<<NB, 256>>>(attn_out);
    k_av     <<<dim3(16, NB), 256>>>(values, attn_out);
    k_context<<<dim3(4, NB), 128>>>(W_value, ctx_out);
}

// round 9
// speedup vs baseline: 1.5645x; 1.0550x over previous
#include <cuda_runtime.h>
#include <cuda_fp16.h>
#include <math.h>
#include <stdint.h>

// Problem constants
#define NB   64
#define NT   1024
#define AD   128
#define RD   1024
#define ED   512
#define NF   32
#define KSZ  31
#define PADW 15

#define KTOT 544          // 512 keys + 32 loc features
#define NCH  17           // 17 chunks of K=32
#define TM   128          // t rows per CTA tile

// Tile stride: 32 fp16 data + 8B pad = 80B rows.
#define TSTRIDE 80
#define TILE_B  (128 * TSTRIDE)
#define NSTAGE  3
#define DYN_BYTES (2 * NSTAGE * TILE_B)   // A0..A2, B0..B2 = 61440 B

#define NPART 32

// ---------------- device scratch ----------------
__device__ __half g_Whf[AD][KTOT];
__device__ __half g_loc[NB][NT][NF];
__device__ float g_qproj[NB][AD];
__device__ float g_scores[NB][NT];
__device__ float g_partial[NB][NPART][ED];

// ---------------- helpers ----------------
__device__ __forceinline__ uint32_t smem_u32(const void* p) {
    uint32_t a;
    asm("{ .reg .u64 t; cvta.to.shared.u64 t, %1; cvt.u32.u64 %0, t; }"
        : "=r"(a) : "l"(p));
    return a;
}
__device__ __forceinline__ void sts64(uint32_t a, uint32_t x, uint32_t y) {
    asm volatile("st.shared.v2.b32 [%0], {%1,%2};" :: "r"(a), "r"(x), "r"(y));
}
__device__ __forceinline__ void cp16(uint32_t dst, const void* src) {
    asm volatile("cp.async.ca.shared.global [%0], [%1], 16;" :: "r"(dst), "l"(src));
}
__device__ __forceinline__ void ldsm4(uint32_t r[4], uint32_t addr) {
    asm volatile("ldmatrix.sync.aligned.m8n8.x4.shared.b16 {%0,%1,%2,%3}, [%4];"
                 : "=r"(r[0]), "=r"(r[1]), "=r"(r[2]), "=r"(r[3]) : "r"(addr));
}
__device__ __forceinline__ void mma_f16(float d[4], const uint32_t a[4],
                                        uint32_t b0, uint32_t b1) {
    asm volatile(
        "mma.sync.aligned.m16n8k16.row.col.f32.f16.f16.f32 "
        "{%0,%1,%2,%3}, {%4,%5,%6,%7}, {%8,%9}, {%0,%1,%2,%3};"
        : "+f"(d[0]), "+f"(d[1]), "+f"(d[2]), "+f"(d[3])
        : "r"(a[0]), "r"(a[1]), "r"(a[2]), "r"(a[3]), "r"(b0), "r"(b1));
}
__device__ __forceinline__ uint32_t pack_h2(float x, float y) {
    __half2 p = __floats2half2_rn(x, y);
    return *(uint32_t*)&p;
}

// ---------------------------------------------------------------------------
// Prep W: fp16 [a][k] weight matrix (W_key^T rows 0..511, W_loc_proj^T 512..543)
__global__ __launch_bounds__(128) void k_prep_w(const float* __restrict__ W_key,
                                                const float* __restrict__ W_loc_proj) {
    int a = blockIdx.x, tid = threadIdx.x;
    for (int k = tid; k < KTOT; k += 128) {
        float v = (k < ED) ? W_key[a * ED + k] : W_loc_proj[a * NF + (k - ED)];
        g_Whf[a][k] = __float2half(v);
    }
}

// ---------------------------------------------------------------------------
__global__ __launch_bounds__(128) void k_prep_q(const float* __restrict__ query,
                                                const float* __restrict__ W_query) {
    __shared__ float q_s[RD];
    int b = blockIdx.x, tid = threadIdx.x;
    #pragma unroll
    for (int i = 0; i < RD / 128; i++)
        q_s[i * 128 + tid] = query[b * RD + i * 128 + tid];
    __syncthreads();
    const float4* wr = (const float4*)(W_query + (size_t)tid * RD);
    float acc = 0.f;
    #pragma unroll 8
    for (int e4 = 0; e4 < RD / 4; e4++) {
        float4 w = wr[e4];
        float4 q = *(const float4*)&q_s[e4 * 4];
        acc += w.x * q.x + w.y * q.y + w.z * q.z + w.w * q.w;
    }
    g_qproj[b][tid] = acc;
}

// ---------------------------------------------------------------------------
// Location conv features -> fp16 g_loc[b][t][f]
__global__ __launch_bounds__(256) void k_loc(const float* __restrict__ awc,
                                             const float* __restrict__ W_loc_conv) {
    __shared__ float awc_s[158];
    __shared__ float Wc_s[NF][KSZ];
    int b = blockIdx.y, t0 = blockIdx.x * 128, tid = threadIdx.x;
    if (tid < 158) {
        int gi = t0 - PADW + tid;
        awc_s[tid] = (gi >= 0 && gi < NT) ? awc[b * NT + gi] : 0.f;
    }
    for (int i = tid; i < NF * KSZ; i += 256)
        Wc_s[i / KSZ][i % KSZ] = W_loc_conv[i];
    __syncthreads();
    #pragma unroll
    for (int j = 0; j < 8; j++) {
        int pidx = tid + 256 * j;           // 2048 half2 outputs
        int r = pidx >> 4, f = (pidx & 15) << 1;
        float s0 = 0.f, s1 = 0.f;
        #pragma unroll
        for (int k = 0; k < KSZ; k++) {
            float av = awc_s[r + k];
            s0 += av * Wc_s[f][k];
            s1 += av * Wc_s[f + 1][k];
        }
        *(__half2*)&g_loc[b][t0 + r][f] = __floats2half2_rn(s0, s1);
    }
}

// ---------------------------------------------------------------------------
// Scores: fp16 m16n8k16, 3-stage pipeline, ONE __syncthreads per K-chunk.
__global__ __launch_bounds__(256, 2) void k_scores(
    const float* __restrict__ keys,
    const float* __restrict__ W_attn,
    const unsigned char* __restrict__ mask)
{
    extern __shared__ char dsm[];
    __shared__ float qp_s[AD];
    __shared__ float wattn_s[AD];
    __shared__ float sred[2][128];

    const int b   = blockIdx.y;
    const int t0  = blockIdx.x * TM;
    const int tid = threadIdx.x;
    const int lane = tid & 31, w = tid >> 5;
    const int g = lane >> 2, tg = lane & 3;
    const int Mb = (w & 3) * 32;
    const int Nb = (w >> 2) * 64;

    const uint32_t base = smem_u32(dsm);
    // stage s: A at s*TILE_B, B at (3+s)*TILE_B
    #define A_ST(s) (base + (uint32_t)(s) * TILE_B)
    #define B_ST(s) (base + (uint32_t)(3 + (s)) * TILE_B)

    const int lm = lane & 15;
    const int lkb = (lane >> 4) * 16;
    const int bn = (lane & 7) + ((lane >> 4) << 3);
    const int bkb = ((lane >> 3) & 1) * 16;

    if (tid < AD) { qp_s[tid] = g_qproj[b][tid]; wattn_s[tid] = W_attn[tid]; }

    // A store mapping
    const int ar = tid >> 3;             // rows 0..31 (+32j)
    const int akq = (tid & 7) << 2;      // 0..28
    const float* kptr = keys + ((size_t)(b * NT + t0 + ar)) * ED + akq;
    // B cp mapping
    const int bnrow = tid >> 2;          // 0..63 (+64j)
    const int bur = tid & 3;
    // loc cp mapping: 512 16B units (128 rows x 4)
    const int lr = tid >> 1;             // 0..127
    const int lu = tid & 1;              // 2 units per thread x2 loop

    float4 ka[4];

    // ---- prologue: stores A(0), A(1); cp B(0), B(1); LDG ka(2) ----
    #pragma unroll
    for (int kc = 0; kc < 2; kc++) {
        #pragma unroll
        for (int j = 0; j < 4; j++) {
            float4 v = *(const float4*)(kptr + (size_t)(32 * j) * ED + kc * 32);
            sts64(A_ST(kc) + (ar + 32 * j) * TSTRIDE + akq * 2,
                  pack_h2(v.x, v.y), pack_h2(v.z, v.w));
        }
        #pragma unroll
        for (int j = 0; j < 2; j++)
            cp16(B_ST(kc) + (bnrow + 64 * j) * TSTRIDE + bur * 16,
                 &g_Whf[bnrow + 64 * j][kc * 32 + bur * 8]);
        asm volatile("cp.async.commit_group;");
    }
    #pragma unroll
    for (int j = 0; j < 4; j++)
        ka[j] = *(const float4*)(kptr + (size_t)(32 * j) * ED + 2 * 32);

    float acc[2][8][4];
    #pragma unroll
    for (int mt = 0; mt < 2; mt++)
        #pragma unroll
        for (int nt = 0; nt < 8; nt++)
            #pragma unroll
            for (int ci = 0; ci < 4; ci++) acc[mt][nt][ci] = 0.f;

    for (int c = 0; c < NCH; c++) {
        const int st  = c % 3;
        const int st2 = (c + 2) % 3;
        asm volatile("cp.async.wait_group 1;");   // B(c) (and loc if c==16) done
        __syncthreads();                          // MMA(c-1) done; stores visible

        // ---- produce stage c+2 ----
        if (c + 2 < 16) {
            #pragma unroll
            for (int j = 0; j < 4; j++)
                sts64(A_ST(st2) + (ar + 32 * j) * TSTRIDE + akq * 2,
                      pack_h2(ka[j].x, ka[j].y), pack_h2(ka[j].z, ka[j].w));
        } else if (c + 2 == 16) {
            // loc-feature chunk direct fp16 cp.async (64B per row)
            #pragma unroll
            for (int j = 0; j < 2; j++)
                cp16(A_ST(st2) + lr * TSTRIDE + (lu + 2 * j) * 16,
                     &g_loc[b][t0 + lr][(lu + 2 * j) * 8]);
        }
        if (c + 3 < 16) {
            #pragma unroll
            for (int j = 0; j < 4; j++)
                ka[j] = *(const float4*)(kptr + (size_t)(32 * j) * ED + (c + 3) * 32);
        }
        if (c + 2 < NCH) {
            #pragma unroll
            for (int j = 0; j < 2; j++)
                cp16(B_ST(st2) + (bnrow + 64 * j) * TSTRIDE + bur * 16,
                     &g_Whf[bnrow + 64 * j][(c + 2) * 32 + bur * 8]);
        }
        asm volatile("cp.async.commit_group;");

        // ---- MMA on stage c ----
        const uint32_t Ab = A_ST(st);
        const uint32_t Bb = B_ST(st);
        #pragma unroll
        for (int k16 = 0; k16 < 2; k16++) {
            uint32_t a[2][4];
            #pragma unroll
            for (int mt = 0; mt < 2; mt++)
                ldsm4(a[mt], Ab + (Mb + mt * 16 + lm) * TSTRIDE + k16 * 32 + lkb);
            #pragma unroll
            for (int g16 = 0; g16 < 4; g16++) {
                uint32_t bb[4];
                ldsm4(bb, Bb + (Nb + g16 * 16 + bn) * TSTRIDE + k16 * 32 + bkb);
                mma_f16(acc[0][2 * g16],     a[0], bb[0], bb[1]);
                mma_f16(acc[1][2 * g16],     a[1], bb[0], bb[1]);
                mma_f16(acc[0][2 * g16 + 1], a[0], bb[2], bb[3]);
                mma_f16(acc[1][2 * g16 + 1], a[1], bb[2], bb[3]);
            }
        }
    }

    // ---- epilogue: tanh + W_attn dot, lane reduce, mask ----
    #pragma unroll
    for (int mt = 0; mt < 2; mt++) {
        #pragma unroll
        for (int h = 0; h < 2; h++) {
            float p = 0.f;
            #pragma unroll
            for (int nt = 0; nt < 8; nt++) {
                int col = Nb + nt * 8 + 2 * tg;
                p += wattn_s[col]     * tanhf(acc[mt][nt][2 * h]     + qp_s[col]);
                p += wattn_s[col + 1] * tanhf(acc[mt][nt][2 * h + 1] + qp_s[col + 1]);
            }
            p += __shfl_xor_sync(0xffffffffu, p, 1);
            p += __shfl_xor_sync(0xffffffffu, p, 2);
            if (tg == 0)
                sred[w >> 2][Mb + mt * 16 + g + 8 * h] = p;
        }
    }
    __syncthreads();
    if (tid < 128) {
        int t = t0 + tid;
        float sc = sred[0][tid] + sred[1][tid];
        if (mask[b * NT + t]) sc = -INFINITY;
        g_scores[b][t] = sc;
    }
    #undef A_ST
    #undef B_ST
}

// ---------------------------------------------------------------------------
__global__ __launch_bounds__(256) void k_softmax(float* __restrict__ attn_out) {
    __shared__ float red[256];
    int b = blockIdx.x, tid = threadIdx.x;
    float v[4];
    float m = -INFINITY;
    #pragma unroll
    for (int i = 0; i < 4; i++) {
        v[i] = g_scores[b][i * 256 + tid];
        m = fmaxf(m, v[i]);
    }
    red[tid] = m; __syncthreads();
    for (int s = 128; s > 0; s >>= 1) {
        if (tid < s) red[tid] = fmaxf(red[tid], red[tid + s]);
        __syncthreads();
    }
    m = red[0]; __syncthreads();
    float sum = 0.f;
    #pragma unroll
    for (int i = 0; i < 4; i++) { v[i] = __expf(v[i] - m); sum += v[i]; }
    red[tid] = sum; __syncthreads();
    for (int s = 128; s > 0; s >>= 1) {
        if (tid < s) red[tid] += red[tid + s];
        __syncthreads();
    }
    float inv = 1.f / red[0];
    #pragma unroll
    for (int i = 0; i < 4; i++)
        attn_out[b * NT + i * 256 + tid] = v[i] * inv;
}

// ---------------------------------------------------------------------------
__global__ __launch_bounds__(256) void k_av(const float* __restrict__ values,
                                            const float* __restrict__ attn) {
    __shared__ float at_s[64];
    int ts = blockIdx.x, b = blockIdx.y, tid = threadIdx.x;
    if (tid < 64) at_s[tid] = attn[b * NT + ts * 64 + tid];
    __syncthreads();
    int cg = tid & 127, half = tid >> 7;
    const float4* vp = (const float4*)
        (values + ((size_t)(b * NT + ts * 64 + half * 32)) * ED);
    float4 a0 = make_float4(0.f, 0.f, 0.f, 0.f);
    float4 a1 = make_float4(0.f, 0.f, 0.f, 0.f);
    #pragma unroll 8
    for (int t = 0; t < 32; t += 2) {
        float w0 = at_s[half * 32 + t];
        float w1 = at_s[half * 32 + t + 1];
        float4 v0 = vp[(size_t)t * (ED / 4) + cg];
        float4 v1 = vp[(size_t)(t + 1) * (ED / 4) + cg];
        a0.x += w0 * v0.x; a0.y += w0 * v0.y; a0.z += w0 * v0.z; a0.w += w0 * v0.w;
        a1.x += w1 * v1.x; a1.y += w1 * v1.y; a1.z += w1 * v1.z; a1.w += w1 * v1.w;
    }
    a0.x += a1.x; a0.y += a1.y; a0.z += a1.z; a0.w += a1.w;
    *(float4*)&g_partial[b][ts * 2 + half][cg * 4] = a0;
}

// ---------------------------------------------------------------------------
__global__ __launch_bounds__(128) void k_context(const float* __restrict__ W_value,
                                                 float* __restrict__ ctx) {
    __shared__ float av_s[ED];
    int fc = blockIdx.x, b = blockIdx.y, tid = threadIdx.x;
    for (int i = tid; i < ED; i += 128) {
        float s = 0.f;
        #pragma unroll
        for (int p = 0; p < NPART; p++) s += g_partial[b][p][i];
        av_s[i] = s;
    }
    __syncthreads();
    int f = fc * 128 + tid;
    const float4* wr = (const float4*)(W_value + (size_t)f * ED);
    float acc = 0.f;
    #pragma unroll 8
    for (int e4 = 0; e4 < ED / 4; e4++) {
        float4 wv = wr[e4];
        float4 a = *(const float4*)&av_s[e4 * 4];
        acc += wv.x * a.x + wv.y * a.y + wv.z * a.z + wv.w * a.w;
    }
    ctx[b * ED + f] = acc;
}

// ---------------------------------------------------------------------------
extern "C" void kernel_launch(void* const* d_in, const int* in_sizes, int n_in,
                              void* d_out, int out_size) {
    const float* query        = (const float*)d_in[0];
    const float* keys         = (const float*)d_in[1];
    const float* values       = (const float*)d_in[2];
    const float* awc          = (const float*)d_in[3];
    const unsigned char* mask = (const unsigned char*)d_in[4];
    const float* W_loc_conv   = (const float*)d_in[5];
    const float* W_loc_proj   = (const float*)d_in[6];
    const float* W_query      = (const float*)d_in[7];
    const float* W_key        = (const float*)d_in[8];
    const float* W_value      = (const float*)d_in[9];
    const float* W_attn       = (const float*)d_in[10];

    float* out      = (float*)d_out;
    float* ctx_out  = out;                 // context: 64*512
    float* attn_out = out + NB * ED;       // attn:    64*1024

    cudaFuncSetAttribute(k_scores, cudaFuncAttributeMaxDynamicSharedMemorySize,
                         DYN_BYTES);

    k_prep_w <<<AD, 128>>>(W_key, W_loc_proj);                     // launch 1
    k_prep_q <<<NB, 128>>>(query, W_query);                        // launch 2
    k_loc    <<<dim3(NT / 128, NB), 256>>>(awc, W_loc_conv);       // launch 3
    k_scores <<<dim3(NT / TM, NB), 256, DYN_BYTES>>>(keys, W_attn, mask); // 4 (profiled)
    k_softmax<<<NB, 256>>>(attn_out);
    k_av     <<<dim3(16, NB), 256>>>(values, attn_out);
    k_context<<<dim3(4, NB), 128>>>(W_value, ctx_out);
}